// round 8
// baseline (speedup 1.0000x reference)
#include <cuda_runtime.h>
#include <cstdint>
#include <math.h>

// Problem constants
#define TT    4096   // tokens = B*S
#define DIN   4096
#define DOUT  4096
#define NE    8
#define NRTR  64     // E * K_RTR
#define N2    320    // [svh(256) | gate(64)]
#define KEXT  288    // 256 (E*K_EXP) + 8 (w->bias) + 24 zero pad -> 9 * BK(32)
#define KSPL  4      // split-K factor for the small fused GEMM

// Scratch (device globals; allocation is forbidden)
__device__ float g_b2[N2 * DIN];              // [svh | gate]
__device__ float g_p[KSPL * TT * N2];         // split-K partials
__device__ float g_aext[TT * KEXT];           // [w*h | w | 0pad]
__device__ float g_bext[DOUT * KEXT];         // [u_flat | bias^T | 0pad]

// ---------------- f32x2 packed-FMA helpers (FFMA2 hardware path) ----------
__device__ __forceinline__ void fma2(uint64_t& d, uint64_t a, uint64_t b) {
    asm("fma.rn.f32x2 %0, %1, %2, %0;" : "+l"(d) : "l"(a), "l"(b));
}
__device__ __forceinline__ uint64_t dup32(float v) {
    uint64_t r;
    asm("mov.b64 %0, {%1, %1};" : "=l"(r) : "f"(v));
    return r;
}
__device__ __forceinline__ float2 unpk(uint64_t v) {
    float2 r;
    asm("mov.b64 {%0, %1}, %2;" : "=f"(r.x), "=f"(r.y) : "l"(v));
    return r;
}

// ---------------------------------------------------------------------------
// g_b2[r, c]: r<256 -> svh, r<320 -> gate row (r-256)
// ---------------------------------------------------------------------------
__global__ void b2_build(const float* __restrict__ svh, const float* __restrict__ gate) {
    int i = blockIdx.x * blockDim.x + threadIdx.x;
    if (i >= N2 * DIN / 4) return;
    int r = i / (DIN / 4);
    const float4* src = (r < 256) ? (const float4*)svh + i
                                  : (const float4*)gate + (i - 256 * (DIN / 4));
    ((float4*)g_b2)[i] = *src;
}

// ---------------------------------------------------------------------------
// g_bext[n, k] = u[e][n][r] (k=e*32+r<256) | expert_bias[e][n] (k=256+e) | 0
// ---------------------------------------------------------------------------
__global__ void bext_kernel(const float* __restrict__ u, const float* __restrict__ eb) {
    int idx = blockIdx.x * blockDim.x + threadIdx.x;
    if (idx >= DOUT * KEXT) return;
    int n = idx / KEXT;
    int k = idx - n * KEXT;
    float v = 0.f;
    if (k < 256) {
        int e = k >> 5, r = k & 31;
        v = u[(e * DOUT + n) * 32 + r];
    } else if (k < 264) {
        v = eb[(k - 256) * DOUT + n];
    }
    g_bext[idx] = v;
}

// ---------------------------------------------------------------------------
// Split-K fused small GEMM: partial[ks][t, n] = x[t, ks-slice] . b2[n, ks-slice]
// BM=64 BN=64 TM=4 TN=4, 256 threads, grid (N2/64, TT/64, KSPL).
// Same proven loader/inner structure as R7 sgemm (f32x2).
// ---------------------------------------------------------------------------
__global__ __launch_bounds__(256) void skgemm(const float* __restrict__ A) {
    constexpr int BK = 16;
    constexpr int LA = 68;
    __shared__ float As[2][BK][LA];
    __shared__ float Bs[2][BK][LA];
    const int tid = threadIdx.x;
    const int tx = tid & 15, ty = tid >> 4;
    const int arow = tid >> 2;
    const int acol = (tid & 3) * 4;
    const int n0 = blockIdx.x * 64;
    const int t0 = blockIdx.y * 64;
    const int koff = blockIdx.z * (DIN / KSPL);

    const float* Ag = A + (size_t)(t0 + arow) * DIN + koff + acol;
    const float* Bg = g_b2 + (size_t)(n0 + arow) * DIN + koff + acol;

    uint64_t acc[2][4];
    #pragma unroll
    for (int i = 0; i < 2; i++)
        #pragma unroll
        for (int j = 0; j < 4; j++) acc[i][j] = 0ull;

    float4 av, bv;
    auto sts = [&](int buf) {
        As[buf][acol + 0][arow] = av.x;
        As[buf][acol + 1][arow] = av.y;
        As[buf][acol + 2][arow] = av.z;
        As[buf][acol + 3][arow] = av.w;
        Bs[buf][acol + 0][arow] = bv.x;
        Bs[buf][acol + 1][arow] = bv.y;
        Bs[buf][acol + 2][arow] = bv.z;
        Bs[buf][acol + 3][arow] = bv.w;
    };

    av = *(const float4*)(Ag);
    bv = *(const float4*)(Bg);
    sts(0);
    __syncthreads();

    const int nk = DIN / KSPL / BK;
    for (int kt = 0; kt < nk; kt++) {
        const int cur = kt & 1;
        if (kt + 1 < nk) {
            av = *(const float4*)(Ag + (kt + 1) * BK);
            bv = *(const float4*)(Bg + (kt + 1) * BK);
        }
        #pragma unroll
        for (int kk = 0; kk < BK; kk++) {
            uint64_t a2[2], bd[4];
            #pragma unroll
            for (int i = 0; i < 2; i++)
                a2[i] = *(const uint64_t*)&As[cur][kk][ty * 4 + 2 * i];
            #pragma unroll
            for (int j = 0; j < 4; j++)
                bd[j] = dup32(Bs[cur][kk][tx * 4 + j]);
            #pragma unroll
            for (int i = 0; i < 2; i++)
                #pragma unroll
                for (int j = 0; j < 4; j++)
                    fma2(acc[i][j], a2[i], bd[j]);
        }
        if (kt + 1 < nk) {
            sts(cur ^ 1);
            __syncthreads();
        }
    }

    float* outp = g_p + (size_t)blockIdx.z * TT * N2;
    const int row0 = t0 + ty * 4;
    const int col0 = n0 + tx * 4;
    #pragma unroll
    for (int i = 0; i < 2; i++)
        #pragma unroll
        for (int j = 0; j < 4; j++) {
            float2 v = unpk(acc[i][j]);
            outp[(size_t)(row0 + 2 * i) * N2 + col0 + j] = v.x;
            outp[(size_t)(row0 + 2 * i + 1) * N2 + col0 + j] = v.y;
        }
}

// ---------------------------------------------------------------------------
// Per-token: reduce partials -> gate logits -> L2 norms -> top2 softmax ->
// write aext row: [w*h (256) | w (8) | 0 (24)]
// ---------------------------------------------------------------------------
__global__ void routing_aext() {
    int t = blockIdx.x * blockDim.x + threadIdx.x;
    if (t >= TT) return;
    const float* p0 = g_p + (size_t)t * N2;

    float rl[NE];
    #pragma unroll
    for (int e = 0; e < NE; e++) {
        float s = 0.f;
        #pragma unroll
        for (int r = 0; r < 8; r++) {
            float gl = 0.f;
            #pragma unroll
            for (int ks = 0; ks < KSPL; ks++)
                gl += p0[(size_t)ks * TT * N2 + 256 + e * 8 + r];
            s += gl * gl;
        }
        rl[e] = sqrtf(s);
    }
    int i1 = 0;
    #pragma unroll
    for (int e = 1; e < NE; e++) if (rl[e] > rl[i1]) i1 = e;
    int i2 = (i1 == 0) ? 1 : 0;
    #pragma unroll
    for (int e = 0; e < NE; e++) if (e != i1 && rl[e] > rl[i2]) i2 = e;
    float e2 = expf(rl[i2] - rl[i1]);
    float inv = 1.f / (1.f + e2);
    float w[NE];
    #pragma unroll
    for (int e = 0; e < NE; e++)
        w[e] = (e == i1) ? inv : ((e == i2) ? e2 * inv : 0.f);

    float* arow = g_aext + (size_t)t * KEXT;
    for (int k = 0; k < 256; k += 4) {
        float4 s0 = *(const float4*)(p0 + k);
        #pragma unroll
        for (int ks = 1; ks < KSPL; ks++) {
            float4 sp = *(const float4*)(p0 + (size_t)ks * TT * N2 + k);
            s0.x += sp.x; s0.y += sp.y; s0.z += sp.z; s0.w += sp.w;
        }
        float we = w[k >> 5];
        s0.x *= we; s0.y *= we; s0.z *= we; s0.w *= we;
        *(float4*)(arow + k) = s0;
    }
    #pragma unroll
    for (int e = 0; e < NE; e++) arow[256 + e] = w[e];
    #pragma unroll
    for (int p = 0; p < 24; p++) arow[264 + p] = 0.f;
}

// ---------------------------------------------------------------------------
// Main fused GEMM (f32x2, BK=32, dynamic smem):
// out = x @ shared_w^T (K=4096) + [h'|w|0] @ [u|bias|0]^T (K=288) + shared_b
// ---------------------------------------------------------------------------
#define MBK 32
#define LROW 132
#define MAIN_SMEM (2 * 2 * MBK * LROW * 4)   // 2 bufs x (A+B) x 32 x 132 floats

__global__ __launch_bounds__(256) void main_gemm(const float* __restrict__ X,
                                                 const float* __restrict__ W,
                                                 const float* __restrict__ Bias,
                                                 float* __restrict__ C) {
    extern __shared__ __align__(16) float sm[];
    // layout: A[buf][kk][m] at sm + buf*(MBK*LROW), B at sm + 2*MBK*LROW + buf*(MBK*LROW)
    float* const Abase = sm;
    float* const Bbase = sm + 2 * MBK * LROW;
    const int tid = threadIdx.x;
    const int tx = tid & 15, ty = tid >> 4;

    uint64_t acc[4][8];
    #pragma unroll
    for (int i = 0; i < 4; i++)
        #pragma unroll
        for (int j = 0; j < 8; j++) acc[i][j] = 0ull;

    float4 av[4], bv[4];
    auto sts = [&](int buf) {
        float* sA = Abase + buf * (MBK * LROW);
        float* sB = Bbase + buf * (MBK * LROW);
        #pragma unroll
        for (int p = 0; p < 4; p++) {
            int idx = tid + p * 256;
            int row = idx >> 3, c4 = (idx & 7) * 4;
            sA[(c4 + 0) * LROW + row] = av[p].x;
            sA[(c4 + 1) * LROW + row] = av[p].y;
            sA[(c4 + 2) * LROW + row] = av[p].z;
            sA[(c4 + 3) * LROW + row] = av[p].w;
            sB[(c4 + 0) * LROW + row] = bv[p].x;
            sB[(c4 + 1) * LROW + row] = bv[p].y;
            sB[(c4 + 2) * LROW + row] = bv[p].z;
            sB[(c4 + 3) * LROW + row] = bv[p].w;
        }
    };

    #pragma unroll 1
    for (int s = 0; s < 2; s++) {
        const float* Ag;
        const float* Bg;
        int ld, nk;
        if (s == 0) {
            Ag = X + (size_t)blockIdx.y * 128 * DIN;
            Bg = W + (size_t)blockIdx.x * 128 * DIN;
            ld = DIN; nk = DIN / MBK;
        } else {
            Ag = g_aext + (size_t)blockIdx.y * 128 * KEXT;
            Bg = g_bext + (size_t)blockIdx.x * 128 * KEXT;
            ld = KEXT; nk = KEXT / MBK;
        }
        const int lrow = tid >> 3;              // 0..31 base row per p-group
        const int lcol = (tid & 7) * 4;
        #pragma unroll
        for (int p = 0; p < 4; p++) {
            av[p] = *(const float4*)(Ag + (size_t)(lrow + p * 32) * ld + lcol);
            bv[p] = *(const float4*)(Bg + (size_t)(lrow + p * 32) * ld + lcol);
        }
        __syncthreads();   // previous segment's compute done before smem reuse
        sts(0);
        __syncthreads();

        for (int kt = 0; kt < nk; kt++) {
            const int cur = kt & 1;
            if (kt + 1 < nk) {
                #pragma unroll
                for (int p = 0; p < 4; p++) {
                    av[p] = *(const float4*)(Ag + (size_t)(lrow + p * 32) * ld
                                             + (kt + 1) * MBK + lcol);
                    bv[p] = *(const float4*)(Bg + (size_t)(lrow + p * 32) * ld
                                             + (kt + 1) * MBK + lcol);
                }
            }
            const float* sA = Abase + cur * (MBK * LROW);
            const float* sB = Bbase + cur * (MBK * LROW);
            #pragma unroll
            for (int kk = 0; kk < MBK; kk++) {
                uint64_t a2[4], bd[8];
                #pragma unroll
                for (int i = 0; i < 4; i++)
                    a2[i] = *(const uint64_t*)&sA[kk * LROW + ty * 8 + 2 * i];
                #pragma unroll
                for (int j = 0; j < 8; j++)
                    bd[j] = dup32(sB[kk * LROW + tx * 8 + j]);
                #pragma unroll
                for (int i = 0; i < 4; i++)
                    #pragma unroll
                    for (int j = 0; j < 8; j++)
                        fma2(acc[i][j], a2[i], bd[j]);
            }
            if (kt + 1 < nk) {
                sts(cur ^ 1);
                __syncthreads();
            }
        }
    }

    const int row0 = blockIdx.y * 128 + ty * 8;
    const int col0 = blockIdx.x * 128 + tx * 8;
    #pragma unroll
    for (int i = 0; i < 4; i++)
        #pragma unroll
        for (int j = 0; j < 8; j++) {
            float2 v = unpk(acc[i][j]);
            float b = Bias[col0 + j];
            C[(size_t)(row0 + 2 * i) * DOUT + col0 + j] = v.x + b;
            C[(size_t)(row0 + 2 * i + 1) * DOUT + col0 + j] = v.y + b;
        }
}

// ---------------------------------------------------------------------------
extern "C" void kernel_launch(void* const* d_in, const int* in_sizes, int n_in,
                              void* d_out, int out_size) {
    const float* x    = (const float*)d_in[0];  // [T, 4096]
    const float* gate = (const float*)d_in[1];  // [64, 4096]
    const float* shw  = (const float*)d_in[2];  // [4096, 4096]
    const float* shb  = (const float*)d_in[3];  // [4096]
    const float* u    = (const float*)d_in[4];  // [8, 4096, 32]
    const float* svh  = (const float*)d_in[5];  // [8, 32, 4096]
    const float* eb   = (const float*)d_in[6];  // [8, 4096]
    float* out = (float*)d_out;                 // [T, 4096]

    cudaFuncSetAttribute(main_gemm, cudaFuncAttributeMaxDynamicSharedMemorySize,
                         MAIN_SMEM);

    b2_build<<<(N2 * DIN / 4 + 255) / 256, 256>>>(svh, gate);
    bext_kernel<<<(DOUT * KEXT + 255) / 256, 256>>>(u, eb);
    skgemm<<<dim3(N2 / 64, TT / 64, KSPL), 256>>>(x);          // gate+h partials
    routing_aext<<<(TT + 255) / 256, 256>>>();                 // reduce+route+aext
    main_gemm<<<dim3(DOUT / 128, TT / 128), 256, MAIN_SMEM>>>(x, shw, shb, out);
}

// round 9
// speedup vs baseline: 1.1643x; 1.1643x over previous
#include <cuda_runtime.h>
#include <cstdint>
#include <math.h>

// Problem constants
#define TT    4096   // tokens = B*S
#define DIN   4096
#define DOUT  4096
#define NE    8
#define NRTR  64     // E * K_RTR
#define N2    320    // [svh(256) | gate(64)]
#define KEXT  272    // 256 (E*K_EXP) + 8 (w->bias) + 8 zero pad -> 17 * BK(16)
#define KSPL  4      // split-K factor for the small fused GEMM

// Scratch (device globals; allocation is forbidden)
__device__ float g_b2[N2 * DIN];              // [svh | gate]
__device__ float g_p[KSPL * TT * N2];         // split-K partials
__device__ float g_w[TT * NE];                // dense routed weights
__device__ float g_aext[TT * KEXT];           // [w*h | w | 0pad]
__device__ float g_bext[DOUT * KEXT];         // [u_flat | bias^T | 0pad]

// ---------------- f32x2 packed-FMA helpers (FFMA2 hardware path) ----------
__device__ __forceinline__ void fma2(uint64_t& d, uint64_t a, uint64_t b) {
    asm("fma.rn.f32x2 %0, %1, %2, %0;" : "+l"(d) : "l"(a), "l"(b));
}
__device__ __forceinline__ uint64_t dup32(float v) {
    uint64_t r;
    asm("mov.b64 %0, {%1, %1};" : "=l"(r) : "f"(v));
    return r;
}
__device__ __forceinline__ float2 unpk(uint64_t v) {
    float2 r;
    asm("mov.b64 {%0, %1}, %2;" : "=f"(r.x), "=f"(r.y) : "l"(v));
    return r;
}

// ---------------------------------------------------------------------------
// g_b2[r, c]: r<256 -> svh, else gate row (r-256)
// ---------------------------------------------------------------------------
__global__ void b2_build(const float* __restrict__ svh, const float* __restrict__ gate) {
    int i = blockIdx.x * blockDim.x + threadIdx.x;
    if (i >= N2 * DIN / 4) return;
    int r = i / (DIN / 4);
    const float4* src = (r < 256) ? (const float4*)svh + i
                                  : (const float4*)gate + (i - 256 * (DIN / 4));
    ((float4*)g_b2)[i] = *src;
}

// ---------------------------------------------------------------------------
// g_bext[n, k] = u[e][n][r] (k=e*32+r<256) | expert_bias[e][n] (k=256+e) | 0
// ---------------------------------------------------------------------------
__global__ void bext_kernel(const float* __restrict__ u, const float* __restrict__ eb) {
    int idx = blockIdx.x * blockDim.x + threadIdx.x;
    if (idx >= DOUT * KEXT) return;
    int n = idx / KEXT;
    int k = idx - n * KEXT;
    float v = 0.f;
    if (k < 256) {
        int e = k >> 5, r = k & 31;
        v = u[(e * DOUT + n) * 32 + r];
    } else if (k < 264) {
        v = eb[(k - 256) * DOUT + n];
    }
    g_bext[idx] = v;
}

// ---------------------------------------------------------------------------
// Split-K fused small GEMM: partial[ks][t, n] = x[t, ks-slice] . b2[n, ks-slice]
// BM=64 BN=64 TM=4 TN=4, 256 threads, grid (N2/64, TT/64, KSPL). (R8-proven)
// ---------------------------------------------------------------------------
__global__ __launch_bounds__(256) void skgemm(const float* __restrict__ A) {
    constexpr int BK = 16;
    constexpr int LA = 68;
    __shared__ float As[2][BK][LA];
    __shared__ float Bs[2][BK][LA];
    const int tid = threadIdx.x;
    const int tx = tid & 15, ty = tid >> 4;
    const int arow = tid >> 2;
    const int acol = (tid & 3) * 4;
    const int n0 = blockIdx.x * 64;
    const int t0 = blockIdx.y * 64;
    const int koff = blockIdx.z * (DIN / KSPL);

    const float* Ag = A + (size_t)(t0 + arow) * DIN + koff + acol;
    const float* Bg = g_b2 + (size_t)(n0 + arow) * DIN + koff + acol;

    uint64_t acc[2][4];
    #pragma unroll
    for (int i = 0; i < 2; i++)
        #pragma unroll
        for (int j = 0; j < 4; j++) acc[i][j] = 0ull;

    float4 av, bv;
    auto sts = [&](int buf) {
        As[buf][acol + 0][arow] = av.x;
        As[buf][acol + 1][arow] = av.y;
        As[buf][acol + 2][arow] = av.z;
        As[buf][acol + 3][arow] = av.w;
        Bs[buf][acol + 0][arow] = bv.x;
        Bs[buf][acol + 1][arow] = bv.y;
        Bs[buf][acol + 2][arow] = bv.z;
        Bs[buf][acol + 3][arow] = bv.w;
    };

    av = *(const float4*)(Ag);
    bv = *(const float4*)(Bg);
    sts(0);
    __syncthreads();

    const int nk = DIN / KSPL / BK;
    for (int kt = 0; kt < nk; kt++) {
        const int cur = kt & 1;
        if (kt + 1 < nk) {
            av = *(const float4*)(Ag + (kt + 1) * BK);
            bv = *(const float4*)(Bg + (kt + 1) * BK);
        }
        #pragma unroll
        for (int kk = 0; kk < BK; kk++) {
            uint64_t a2[2], bd[4];
            #pragma unroll
            for (int i = 0; i < 2; i++)
                a2[i] = *(const uint64_t*)&As[cur][kk][ty * 4 + 2 * i];
            #pragma unroll
            for (int j = 0; j < 4; j++)
                bd[j] = dup32(Bs[cur][kk][tx * 4 + j]);
            #pragma unroll
            for (int i = 0; i < 2; i++)
                #pragma unroll
                for (int j = 0; j < 4; j++)
                    fma2(acc[i][j], a2[i], bd[j]);
        }
        if (kt + 1 < nk) {
            sts(cur ^ 1);
            __syncthreads();
        }
    }

    float* outp = g_p + (size_t)blockIdx.z * TT * N2;
    const int row0 = t0 + ty * 4;
    const int col0 = n0 + tx * 4;
    #pragma unroll
    for (int i = 0; i < 2; i++)
        #pragma unroll
        for (int j = 0; j < 4; j++) {
            float2 v = unpk(acc[i][j]);
            outp[(size_t)(row0 + 2 * i) * N2 + col0 + j] = v.x;
            outp[(size_t)(row0 + 2 * i + 1) * N2 + col0 + j] = v.y;
        }
}

// ---------------------------------------------------------------------------
// Routing only: reduce the 64 gate-logit partials per token -> top2 softmax.
// ---------------------------------------------------------------------------
__global__ void routing_w() {
    int t = blockIdx.x * blockDim.x + threadIdx.x;
    if (t >= TT) return;
    const float* p0 = g_p + (size_t)t * N2 + 256;
    float rl[NE];
    #pragma unroll
    for (int e = 0; e < NE; e++) {
        float s = 0.f;
        #pragma unroll
        for (int r = 0; r < 8; r++) {
            float gl = 0.f;
            #pragma unroll
            for (int ks = 0; ks < KSPL; ks++)
                gl += p0[(size_t)ks * TT * N2 + e * 8 + r];
            s += gl * gl;
        }
        rl[e] = sqrtf(s);
    }
    int i1 = 0;
    #pragma unroll
    for (int e = 1; e < NE; e++) if (rl[e] > rl[i1]) i1 = e;
    int i2 = (i1 == 0) ? 1 : 0;
    #pragma unroll
    for (int e = 0; e < NE; e++) if (e != i1 && rl[e] > rl[i2]) i2 = e;
    float e2 = expf(rl[i2] - rl[i1]);
    float inv = 1.f / (1.f + e2);
    #pragma unroll
    for (int e = 0; e < NE; e++)
        g_w[t * NE + e] = (e == i1) ? inv : ((e == i2) ? e2 * inv : 0.f);
}

// ---------------------------------------------------------------------------
// aext rows, fully parallel: one float4 per thread. 272/4 = 68 float4/token.
// k4 < 64: reduce KSPL h-partials, scale by w; k4 64-65: w slots; 66-67: 0.
// ---------------------------------------------------------------------------
__global__ void aext_build() {
    int idx = blockIdx.x * blockDim.x + threadIdx.x;
    if (idx >= TT * (KEXT / 4)) return;
    int t = idx / (KEXT / 4);
    int k4 = idx - t * (KEXT / 4);
    float4 v;
    if (k4 < 64) {
        const float* p0 = g_p + (size_t)t * N2 + k4 * 4;
        v = *(const float4*)(p0);
        #pragma unroll
        for (int ks = 1; ks < KSPL; ks++) {
            float4 sp = *(const float4*)(p0 + (size_t)ks * TT * N2);
            v.x += sp.x; v.y += sp.y; v.z += sp.z; v.w += sp.w;
        }
        float we = g_w[t * NE + (k4 >> 3)];
        v.x *= we; v.y *= we; v.z *= we; v.w *= we;
    } else if (k4 < 66) {
        const float* wp = g_w + t * NE + (k4 - 64) * 4;
        v = make_float4(wp[0], wp[1], wp[2], wp[3]);
    } else {
        v = make_float4(0.f, 0.f, 0.f, 0.f);
    }
    *(float4*)(g_aext + (size_t)t * KEXT + k4 * 4) = v;
}

// ---------------------------------------------------------------------------
// Main fused GEMM (f32x2, BK=16 — R7-proven verbatim):
// out = x @ shared_w^T (K=4096) + [h'|w|0] @ [u|bias|0]^T (K=272) + shared_b
// ---------------------------------------------------------------------------
__global__ __launch_bounds__(256) void main_gemm(const float* __restrict__ X,
                                                 const float* __restrict__ W,
                                                 const float* __restrict__ Bias,
                                                 float* __restrict__ C) {
    constexpr int BK = 16;
    constexpr int LA = 132, LB = 132;
    __shared__ float As[2][BK][LA];
    __shared__ float Bs[2][BK][LB];
    const int tid = threadIdx.x;
    const int tx = tid & 15, ty = tid >> 4;
    const int arow = tid >> 2;
    const int acol = (tid & 3) * 4;

    uint64_t acc[4][8];
    #pragma unroll
    for (int i = 0; i < 4; i++)
        #pragma unroll
        for (int j = 0; j < 8; j++) acc[i][j] = 0ull;

    float4 av[2], bv[2];
    auto sts = [&](int buf) {
        #pragma unroll
        for (int p = 0; p < 2; p++) {
            As[buf][acol + 0][arow + p * 64] = av[p].x;
            As[buf][acol + 1][arow + p * 64] = av[p].y;
            As[buf][acol + 2][arow + p * 64] = av[p].z;
            As[buf][acol + 3][arow + p * 64] = av[p].w;
            Bs[buf][acol + 0][arow + p * 64] = bv[p].x;
            Bs[buf][acol + 1][arow + p * 64] = bv[p].y;
            Bs[buf][acol + 2][arow + p * 64] = bv[p].z;
            Bs[buf][acol + 3][arow + p * 64] = bv[p].w;
        }
    };

    #pragma unroll 1
    for (int s = 0; s < 2; s++) {
        const float* Ag;
        const float* Bg;
        int ld, nk;
        if (s == 0) {
            Ag = X + (size_t)(blockIdx.y * 128 + arow) * DIN + acol;
            Bg = W + (size_t)(blockIdx.x * 128 + arow) * DIN + acol;
            ld = DIN; nk = DIN / BK;
        } else {
            Ag = g_aext + (size_t)(blockIdx.y * 128 + arow) * KEXT + acol;
            Bg = g_bext + (size_t)(blockIdx.x * 128 + arow) * KEXT + acol;
            ld = KEXT; nk = KEXT / BK;
        }
        av[0] = *(const float4*)(Ag);
        av[1] = *(const float4*)(Ag + (size_t)64 * ld);
        bv[0] = *(const float4*)(Bg);
        bv[1] = *(const float4*)(Bg + (size_t)64 * ld);
        __syncthreads();   // previous segment's last compute must finish before reuse
        sts(0);
        __syncthreads();

        for (int kt = 0; kt < nk; kt++) {
            const int cur = kt & 1;
            if (kt + 1 < nk) {
                av[0] = *(const float4*)(Ag + (kt + 1) * BK);
                av[1] = *(const float4*)(Ag + (kt + 1) * BK + (size_t)64 * ld);
                bv[0] = *(const float4*)(Bg + (kt + 1) * BK);
                bv[1] = *(const float4*)(Bg + (kt + 1) * BK + (size_t)64 * ld);
            }
            #pragma unroll
            for (int kk = 0; kk < BK; kk++) {
                uint64_t a2[4], bd[8];
                #pragma unroll
                for (int i = 0; i < 4; i++)
                    a2[i] = *(const uint64_t*)&As[cur][kk][ty * 8 + 2 * i];
                #pragma unroll
                for (int j = 0; j < 8; j++)
                    bd[j] = dup32(Bs[cur][kk][tx * 8 + j]);
                #pragma unroll
                for (int i = 0; i < 4; i++)
                    #pragma unroll
                    for (int j = 0; j < 8; j++)
                        fma2(acc[i][j], a2[i], bd[j]);
            }
            if (kt + 1 < nk) {
                sts(cur ^ 1);
                __syncthreads();
            }
        }
    }

    const int row0 = blockIdx.y * 128 + ty * 8;
    const int col0 = blockIdx.x * 128 + tx * 8;
    #pragma unroll
    for (int i = 0; i < 4; i++)
        #pragma unroll
        for (int j = 0; j < 8; j++) {
            float2 v = unpk(acc[i][j]);
            float b = Bias[col0 + j];
            C[(size_t)(row0 + 2 * i) * DOUT + col0 + j] = v.x + b;
            C[(size_t)(row0 + 2 * i + 1) * DOUT + col0 + j] = v.y + b;
        }
}

// ---------------------------------------------------------------------------
extern "C" void kernel_launch(void* const* d_in, const int* in_sizes, int n_in,
                              void* d_out, int out_size) {
    const float* x    = (const float*)d_in[0];  // [T, 4096]
    const float* gate = (const float*)d_in[1];  // [64, 4096]
    const float* shw  = (const float*)d_in[2];  // [4096, 4096]
    const float* shb  = (const float*)d_in[3];  // [4096]
    const float* u    = (const float*)d_in[4];  // [8, 4096, 32]
    const float* svh  = (const float*)d_in[5];  // [8, 32, 4096]
    const float* eb   = (const float*)d_in[6];  // [8, 4096]
    float* out = (float*)d_out;                 // [T, 4096]

    b2_build<<<(N2 * DIN / 4 + 255) / 256, 256>>>(svh, gate);
    bext_kernel<<<(DOUT * KEXT + 255) / 256, 256>>>(u, eb);
    skgemm<<<dim3(N2 / 64, TT / 64, KSPL), 256>>>(x);          // gate+h partials
    routing_w<<<(TT + 255) / 256, 256>>>();                    // top2 weights
    aext_build<<<(TT * (KEXT / 4) + 255) / 256, 256>>>();      // aext rows
    main_gemm<<<dim3(DOUT / 128, TT / 128), 256>>>(x, shw, shb, out);
}

// round 10
// speedup vs baseline: 1.1963x; 1.0275x over previous
#include <cuda_runtime.h>
#include <cstdint>
#include <math.h>

// Problem constants
#define TT    4096   // tokens = B*S
#define DIN   4096
#define DOUT  4096
#define NE    8
#define N2    320    // [svh(256) | gate(64)]
#define KEXT  272    // 256 (E*K_EXP) + 8 (w->bias) + 8 zero pad -> 17 * BK(16)
#define KSPL  4      // split-K factor for the small fused GEMM

// Scratch (device globals; allocation is forbidden)
__device__ float g_b2[N2 * DIN];              // [svh | gate]
__device__ float g_p[KSPL * TT * N2];         // split-K partials
__device__ float g_rl[TT * NE];               // router L2 norms
__device__ float g_w[TT * NE];                // dense routed weights
__device__ float g_aext[TT * KEXT];           // [w*h | w | 0pad]
__device__ float g_bext[DOUT * KEXT];         // [u_flat | bias^T | 0pad]

// ---------------- f32x2 packed-FMA helpers (FFMA2 hardware path) ----------
__device__ __forceinline__ void fma2(uint64_t& d, uint64_t a, uint64_t b) {
    asm("fma.rn.f32x2 %0, %1, %2, %0;" : "+l"(d) : "l"(a), "l"(b));
}
__device__ __forceinline__ uint64_t dup32(float v) {
    uint64_t r;
    asm("mov.b64 %0, {%1, %1};" : "=l"(r) : "f"(v));
    return r;
}
__device__ __forceinline__ float2 unpk(uint64_t v) {
    float2 r;
    asm("mov.b64 {%0, %1}, %2;" : "=f"(r.x), "=f"(r.y) : "l"(v));
    return r;
}

// ---------------------------------------------------------------------------
__global__ void b2_build(const float* __restrict__ svh, const float* __restrict__ gate) {
    int i = blockIdx.x * blockDim.x + threadIdx.x;
    if (i >= N2 * DIN / 4) return;
    int r = i / (DIN / 4);
    const float4* src = (r < 256) ? (const float4*)svh + i
                                  : (const float4*)gate + (i - 256 * (DIN / 4));
    ((float4*)g_b2)[i] = *src;
}

__global__ void bext_kernel(const float* __restrict__ u, const float* __restrict__ eb) {
    int idx = blockIdx.x * blockDim.x + threadIdx.x;
    if (idx >= DOUT * KEXT) return;
    int n = idx / KEXT;
    int k = idx - n * KEXT;
    float v = 0.f;
    if (k < 256) {
        int e = k >> 5, r = k & 31;
        v = u[(e * DOUT + n) * 32 + r];
    } else if (k < 264) {
        v = eb[(k - 256) * DOUT + n];
    }
    g_bext[idx] = v;
}

// ---------------------------------------------------------------------------
// Split-K fused small GEMM (R8-proven verbatim)
// ---------------------------------------------------------------------------
__global__ __launch_bounds__(256) void skgemm(const float* __restrict__ A) {
    constexpr int BK = 16;
    constexpr int LA = 68;
    __shared__ float As[2][BK][LA];
    __shared__ float Bs[2][BK][LA];
    const int tid = threadIdx.x;
    const int tx = tid & 15, ty = tid >> 4;
    const int arow = tid >> 2;
    const int acol = (tid & 3) * 4;
    const int n0 = blockIdx.x * 64;
    const int t0 = blockIdx.y * 64;
    const int koff = blockIdx.z * (DIN / KSPL);

    const float* Ag = A + (size_t)(t0 + arow) * DIN + koff + acol;
    const float* Bg = g_b2 + (size_t)(n0 + arow) * DIN + koff + acol;

    uint64_t acc[2][4];
    #pragma unroll
    for (int i = 0; i < 2; i++)
        #pragma unroll
        for (int j = 0; j < 4; j++) acc[i][j] = 0ull;

    float4 av, bv;
    auto sts = [&](int buf) {
        As[buf][acol + 0][arow] = av.x;
        As[buf][acol + 1][arow] = av.y;
        As[buf][acol + 2][arow] = av.z;
        As[buf][acol + 3][arow] = av.w;
        Bs[buf][acol + 0][arow] = bv.x;
        Bs[buf][acol + 1][arow] = bv.y;
        Bs[buf][acol + 2][arow] = bv.z;
        Bs[buf][acol + 3][arow] = bv.w;
    };

    av = *(const float4*)(Ag);
    bv = *(const float4*)(Bg);
    sts(0);
    __syncthreads();

    const int nk = DIN / KSPL / BK;
    for (int kt = 0; kt < nk; kt++) {
        const int cur = kt & 1;
        if (kt + 1 < nk) {
            av = *(const float4*)(Ag + (kt + 1) * BK);
            bv = *(const float4*)(Bg + (kt + 1) * BK);
        }
        #pragma unroll
        for (int kk = 0; kk < BK; kk++) {
            uint64_t a2[2], bd[4];
            #pragma unroll
            for (int i = 0; i < 2; i++)
                a2[i] = *(const uint64_t*)&As[cur][kk][ty * 4 + 2 * i];
            #pragma unroll
            for (int j = 0; j < 4; j++)
                bd[j] = dup32(Bs[cur][kk][tx * 4 + j]);
            #pragma unroll
            for (int i = 0; i < 2; i++)
                #pragma unroll
                for (int j = 0; j < 4; j++)
                    fma2(acc[i][j], a2[i], bd[j]);
        }
        if (kt + 1 < nk) {
            sts(cur ^ 1);
            __syncthreads();
        }
    }

    float* outp = g_p + (size_t)blockIdx.z * TT * N2;
    const int row0 = t0 + ty * 4;
    const int col0 = n0 + tx * 4;
    #pragma unroll
    for (int i = 0; i < 2; i++)
        #pragma unroll
        for (int j = 0; j < 4; j++) {
            float2 v = unpk(acc[i][j]);
            outp[(size_t)(row0 + 2 * i) * N2 + col0 + j] = v.x;
            outp[(size_t)(row0 + 2 * i + 1) * N2 + col0 + j] = v.y;
        }
}

// ---------------------------------------------------------------------------
// Routing pass 1 (wide): one thread per (token, expert) -> L2 norm.
// ---------------------------------------------------------------------------
__global__ void rl_kernel() {
    int idx = blockIdx.x * blockDim.x + threadIdx.x;
    if (idx >= TT * NE) return;
    int t = idx >> 3, e = idx & 7;
    const float* p0 = g_p + (size_t)t * N2 + 256 + e * 8;
    float s = 0.f;
    #pragma unroll
    for (int r = 0; r < 8; r++) {
        float gl = 0.f;
        #pragma unroll
        for (int ks = 0; ks < KSPL; ks++)
            gl += p0[(size_t)ks * TT * N2 + r];
        s += gl * gl;
    }
    g_rl[idx] = sqrtf(s);
}

// Routing pass 2: per-token top2 softmax.
__global__ void finalize_w() {
    int t = blockIdx.x * blockDim.x + threadIdx.x;
    if (t >= TT) return;
    float rl[NE];
    #pragma unroll
    for (int e = 0; e < NE; e++) rl[e] = g_rl[t * NE + e];
    int i1 = 0;
    #pragma unroll
    for (int e = 1; e < NE; e++) if (rl[e] > rl[i1]) i1 = e;
    int i2 = (i1 == 0) ? 1 : 0;
    #pragma unroll
    for (int e = 0; e < NE; e++) if (e != i1 && rl[e] > rl[i2]) i2 = e;
    float e2 = expf(rl[i2] - rl[i1]);
    float inv = 1.f / (1.f + e2);
    #pragma unroll
    for (int e = 0; e < NE; e++)
        g_w[t * NE + e] = (e == i1) ? inv : ((e == i2) ? e2 * inv : 0.f);
}

// ---------------------------------------------------------------------------
// aext rows, fully parallel: one float4 per thread (R9-proven).
// ---------------------------------------------------------------------------
__global__ void aext_build() {
    int idx = blockIdx.x * blockDim.x + threadIdx.x;
    if (idx >= TT * (KEXT / 4)) return;
    int t = idx / (KEXT / 4);
    int k4 = idx - t * (KEXT / 4);
    float4 v;
    if (k4 < 64) {
        const float* p0 = g_p + (size_t)t * N2 + k4 * 4;
        v = *(const float4*)(p0);
        #pragma unroll
        for (int ks = 1; ks < KSPL; ks++) {
            float4 sp = *(const float4*)(p0 + (size_t)ks * TT * N2);
            v.x += sp.x; v.y += sp.y; v.z += sp.z; v.w += sp.w;
        }
        float we = g_w[t * NE + (k4 >> 3)];
        v.x *= we; v.y *= we; v.z *= we; v.w *= we;
    } else if (k4 < 66) {
        const float* wp = g_w + t * NE + (k4 - 64) * 4;
        v = make_float4(wp[0], wp[1], wp[2], wp[3]);
    } else {
        v = make_float4(0.f, 0.f, 0.f, 0.f);
    }
    *(float4*)(g_aext + (size_t)t * KEXT + k4 * 4) = v;
}

// ---------------------------------------------------------------------------
// Main fused GEMM (f32x2, BK=16), R10 changes:
//  - __launch_bounds__(256, 2): 2 CTAs/SM for latency overlap
//  - B smem in 9-float groups: conflict-free fragment reads
//  - A fragment reads via LDS.128 (broadcast)
// out = x @ shared_w^T (K=4096) + [h'|w|0] @ [u|bias|0]^T (K=272) + shared_b
// ---------------------------------------------------------------------------
#define LA 132
#define LBR 144   // 16 groups x 9 floats per kk-row

__global__ __launch_bounds__(256, 2) void main_gemm(const float* __restrict__ X,
                                                    const float* __restrict__ W,
                                                    const float* __restrict__ Bias,
                                                    float* __restrict__ C) {
    constexpr int BK = 16;
    __shared__ __align__(16) float As[2][BK][LA];
    __shared__ __align__(16) float Bs[2][BK][LBR];
    const int tid = threadIdx.x;
    const int tx = tid & 15, ty = tid >> 4;
    const int arow = tid >> 2;
    const int acol = (tid & 3) * 4;
    const int bslot = ((arow >> 3) * 9) + (arow & 7);  // 9-float group slot

    uint64_t acc[4][8];
    #pragma unroll
    for (int i = 0; i < 4; i++)
        #pragma unroll
        for (int j = 0; j < 8; j++) acc[i][j] = 0ull;

    float4 av[2], bv[2];
    auto sts = [&](int buf) {
        #pragma unroll
        for (int p = 0; p < 2; p++) {
            As[buf][acol + 0][arow + p * 64] = av[p].x;
            As[buf][acol + 1][arow + p * 64] = av[p].y;
            As[buf][acol + 2][arow + p * 64] = av[p].z;
            As[buf][acol + 3][arow + p * 64] = av[p].w;
            Bs[buf][acol + 0][bslot + p * 72] = bv[p].x;
            Bs[buf][acol + 1][bslot + p * 72] = bv[p].y;
            Bs[buf][acol + 2][bslot + p * 72] = bv[p].z;
            Bs[buf][acol + 3][bslot + p * 72] = bv[p].w;
        }
    };

    #pragma unroll 1
    for (int s = 0; s < 2; s++) {
        const float* Ag;
        const float* Bg;
        int ld, nk;
        if (s == 0) {
            Ag = X + (size_t)(blockIdx.y * 128 + arow) * DIN + acol;
            Bg = W + (size_t)(blockIdx.x * 128 + arow) * DIN + acol;
            ld = DIN; nk = DIN / BK;
        } else {
            Ag = g_aext + (size_t)(blockIdx.y * 128 + arow) * KEXT + acol;
            Bg = g_bext + (size_t)(blockIdx.x * 128 + arow) * KEXT + acol;
            ld = KEXT; nk = KEXT / BK;
        }
        av[0] = *(const float4*)(Ag);
        av[1] = *(const float4*)(Ag + (size_t)64 * ld);
        bv[0] = *(const float4*)(Bg);
        bv[1] = *(const float4*)(Bg + (size_t)64 * ld);
        __syncthreads();   // previous segment's last compute must finish before reuse
        sts(0);
        __syncthreads();

        for (int kt = 0; kt < nk; kt++) {
            const int cur = kt & 1;
            if (kt + 1 < nk) {
                av[0] = *(const float4*)(Ag + (kt + 1) * BK);
                av[1] = *(const float4*)(Ag + (kt + 1) * BK + (size_t)64 * ld);
                bv[0] = *(const float4*)(Bg + (kt + 1) * BK);
                bv[1] = *(const float4*)(Bg + (kt + 1) * BK + (size_t)64 * ld);
            }
            #pragma unroll
            for (int kk = 0; kk < BK; kk++) {
                uint64_t a2[4], bd[8];
                {
                    ulonglong2 p0 = *(const ulonglong2*)&As[cur][kk][ty * 8];
                    ulonglong2 p1 = *(const ulonglong2*)&As[cur][kk][ty * 8 + 4];
                    a2[0] = p0.x; a2[1] = p0.y; a2[2] = p1.x; a2[3] = p1.y;
                }
                #pragma unroll
                for (int j = 0; j < 8; j++)
                    bd[j] = dup32(Bs[cur][kk][tx * 9 + j]);
                #pragma unroll
                for (int i = 0; i < 4; i++)
                    #pragma unroll
                    for (int j = 0; j < 8; j++)
                        fma2(acc[i][j], a2[i], bd[j]);
            }
            if (kt + 1 < nk) {
                sts(cur ^ 1);
                __syncthreads();
            }
        }
    }

    const int row0 = blockIdx.y * 128 + ty * 8;
    const int col0 = blockIdx.x * 128 + tx * 8;
    #pragma unroll
    for (int i = 0; i < 4; i++)
        #pragma unroll
        for (int j = 0; j < 8; j++) {
            float2 v = unpk(acc[i][j]);
            float b = Bias[col0 + j];
            C[(size_t)(row0 + 2 * i) * DOUT + col0 + j] = v.x + b;
            C[(size_t)(row0 + 2 * i + 1) * DOUT + col0 + j] = v.y + b;
        }
}

// ---------------------------------------------------------------------------
extern "C" void kernel_launch(void* const* d_in, const int* in_sizes, int n_in,
                              void* d_out, int out_size) {
    const float* x    = (const float*)d_in[0];  // [T, 4096]
    const float* gate = (const float*)d_in[1];  // [64, 4096]
    const float* shw  = (const float*)d_in[2];  // [4096, 4096]
    const float* shb  = (const float*)d_in[3];  // [4096]
    const float* u    = (const float*)d_in[4];  // [8, 4096, 32]
    const float* svh  = (const float*)d_in[5];  // [8, 32, 4096]
    const float* eb   = (const float*)d_in[6];  // [8, 4096]
    float* out = (float*)d_out;                 // [T, 4096]

    static int once = 0;
    if (!once) {
        cudaFuncSetAttribute(main_gemm,
                             cudaFuncAttributePreferredSharedMemoryCarveout, 100);
        once = 1;
    }

    b2_build<<<(N2 * DIN / 4 + 255) / 256, 256>>>(svh, gate);
    bext_kernel<<<(DOUT * KEXT + 255) / 256, 256>>>(u, eb);
    skgemm<<<dim3(N2 / 64, TT / 64, KSPL), 256>>>(x);          // gate+h partials
    rl_kernel<<<(TT * NE + 255) / 256, 256>>>();               // router norms
    finalize_w<<<(TT + 255) / 256, 256>>>();                   // top2 weights
    aext_build<<<(TT * (KEXT / 4) + 255) / 256, 256>>>();      // aext rows
    main_gemm<<<dim3(DOUT / 128, TT / 128), 256>>>(x, shw, shb, out);
}